// round 5
// baseline (speedup 1.0000x reference)
#include <cuda_runtime.h>
#include <cstdint>

// SpatialGradientLoss3D = mean |sobel3d(pred - target)| over 3 axes.
// R5: cp.async 3-stage ring of raw P/T planes (depth-2 prefetch) +
// two-stage consumer: stage A computes w-conv (ws/wd) ONCE per plane row
// into smem; stage B does 6x LDS.128 + h-combine + z-combine.
// __launch_bounds__(256,4) for 32 warps/SM.
// Shapes fixed: (B=4, C=4, D=64, H=128, W=128), fp32, out = 1 float.

#define D_DIM 64
#define H_DIM 128
#define W_DIM 128
#define HW    (H_DIM * W_DIM)
#define BC_DIM 16
#define TH 8                    // output rows per block
#define PR (TH + 2)             // 10 plane rows incl. h halo
#define ZC 16                   // z outputs per block
#define NP (ZC + 2)             // 18 planes touched
#define NSTAGE 3
#define PLANE_F4 (2 * PR * 32)  // 640 float4 per ring stage (P then T)
#define STAGE_BYTES (PLANE_F4 * 16)   // 10240

__global__ void sg3d_zero_out(float* out) { out[0] = 0.0f; }

__device__ __forceinline__ void cpasync16(uint32_t dst, const float* src, int sz) {
    asm volatile("cp.async.cg.shared.global [%0], [%1], 16, %2;\n"
                 :: "r"(dst), "l"(src), "r"(sz) : "memory");
}
__device__ __forceinline__ void cp_commit() {
    asm volatile("cp.async.commit_group;\n" ::: "memory");
}
__device__ __forceinline__ void cp_wait1() {
    asm volatile("cp.async.wait_group 1;\n" ::: "memory");
}

__shared__ float4 sbuf[NSTAGE][PLANE_F4];   // raw P,T ring
__shared__ float4 sws[PR][32];              // w-smooth of e
__shared__ float4 swd[PR][32];              // w-deriv  of e
__shared__ float wsum_sm[8];

// Stage A for one row: read raw P/T from ring stage, compute ws/wd, store.
template<int S>
__device__ __forceinline__ void stageA_row(int row, int lane) {
    const float4* sb = &sbuf[S][0];
    float4 p = sb[row * 32 + lane];
    float4 t = sb[PR * 32 + row * 32 + lane];
    float e0 = p.x - t.x, e1 = p.y - t.y, e2 = p.z - t.z, e3 = p.w - t.w;
    float eL = __shfl_up_sync(0xffffffffu, e3, 1);
    float eR = __shfl_down_sync(0xffffffffu, e0, 1);
    if (lane == 0)  eL = 0.f;
    if (lane == 31) eR = 0.f;
    float4 ws, wd;
    ws.x = eL + 2.f * e0 + e1;
    ws.y = e0 + 2.f * e1 + e2;
    ws.z = e1 + 2.f * e2 + e3;
    ws.w = e2 + 2.f * e3 + eR;
    wd.x = e1 - eL;
    wd.y = e2 - e0;
    wd.z = e3 - e1;
    wd.w = eR - e2;
    sws[row][lane] = ws;
    swd[row][lane] = wd;
}

// Stage B: h-combine into slot S.
template<int S>
__device__ __forceinline__ void stageB(int warp, int lane,
                                       float4* ss, float4* ds, float4* sd) {
    float4 m  = sws[warp][lane];
    float4 c  = sws[warp + 1][lane];
    float4 p  = sws[warp + 2][lane];
    float4 dm = swd[warp][lane];
    float4 dc = swd[warp + 1][lane];
    float4 dp = swd[warp + 2][lane];
    float* ssp = (float*)&ss[S];
    float* dsp = (float*)&ds[S];
    float* sdp = (float*)&sd[S];
    const float *mf = (const float*)&m, *cf = (const float*)&c, *pf = (const float*)&p;
    const float *dmf = (const float*)&dm, *dcf = (const float*)&dc, *dpf = (const float*)&dp;
#pragma unroll
    for (int i = 0; i < 4; ++i) {
        ssp[i] = mf[i] + 2.f * cf[i] + pf[i];
        dsp[i] = pf[i] - mf[i];
        sdp[i] = dmf[i] + 2.f * dcf[i] + dpf[i];
    }
}

template<int SP>
__device__ __forceinline__ void z_combine(const float4* ss, const float4* ds,
                                          const float4* sd, float4& acc) {
    constexpr int SM = (SP + 1) % 3;
    constexpr int S0 = (SP + 2) % 3;
    const float* sm_s = (const float*)&ss[SM];
    const float* sp_s = (const float*)&ss[SP];
    const float* dm = (const float*)&ds[SM];
    const float* d0 = (const float*)&ds[S0];
    const float* dp = (const float*)&ds[SP];
    const float* wm = (const float*)&sd[SM];
    const float* w0 = (const float*)&sd[S0];
    const float* wp = (const float*)&sd[SP];
    float* a = (float*)&acc;
#pragma unroll
    for (int i = 0; i < 4; ++i) {
        float gd = sp_s[i] - sm_s[i];
        float gh = dm[i] + 2.f * d0[i] + dp[i];
        float gw = wm[i] + 2.f * w0[i] + wp[i];
        a[i] += fabsf(gd) + fabsf(gh) + fabsf(gw);
    }
}

__global__ __launch_bounds__(256, 4)
void sg3d_loss_kernel(const float* __restrict__ pred,
                      const float* __restrict__ tgt,
                      float* __restrict__ out) {
    const int tid  = threadIdx.x;
    const int lane = tid & 31;
    const int warp = tid >> 5;          // 0..7 = output row

    const int h0 = blockIdx.x * TH;
    const int bc = blockIdx.y;
    const int z0 = blockIdx.z * ZC;

    const size_t base = (size_t)bc * D_DIM * HW;
    const float* P = pred + base;
    const float* T = tgt + base;

    uint32_t smem_base;
    asm("{ .reg .u64 t; cvta.to.shared.u64 t, %1; cvt.u32.u64 %0, t; }"
        : "=r"(smem_base) : "l"((const void*)&sbuf[0][0]));

    // ---- per-slot cp.async params (hoisted); slot k covers idx = tid+256k ----
    const float* gp[3];
    uint32_t saddr[3];
    int rowok[3], active[3];
#pragma unroll
    for (int k = 0; k < 3; ++k) {
        int idx = tid + 256 * k;
        active[k] = idx < PLANE_F4;
        int a   = idx >= PR * 32;
        int rel = idx - a * PR * 32;
        int row = rel >> 5;
        int c4  = rel & 31;
        int gh  = h0 - 1 + row;
        rowok[k] = (unsigned)gh < (unsigned)H_DIM;
        int soff = (rowok[k] ? gh : 0) * W_DIM + c4 * 4;
        gp[k] = (a ? T : P) + soff;
        saddr[k] = smem_base + (uint32_t)idx * 16u;
    }

    const bool hasA2 = (warp < 2);       // warps 0,1 also do rows 8,9
    const int rowA2 = warp + 8;

#define ISSUE_PLANE(J, STAGE)                                                 \
    do {                                                                      \
        int gz_ = z0 - 1 + (J);                                               \
        int zok_ = (unsigned)gz_ < (unsigned)D_DIM;                           \
        int gzc_ = zok_ ? gz_ : 0;                                            \
        _Pragma("unroll")                                                     \
        for (int k = 0; k < 3; ++k) {                                         \
            if (active[k]) {                                                  \
                int sz_ = (rowok[k] & zok_) ? 16 : 0;                         \
                cpasync16(saddr[k] + (STAGE) * STAGE_BYTES,                   \
                          gp[k] + (size_t)gzc_ * HW, sz_);                    \
            }                                                                 \
        }                                                                     \
    } while (0)

    float4 ss[3], ds[3], sd[3];
    float4 acc = make_float4(0.f, 0.f, 0.f, 0.f);

    // prologue: planes 0,1 -> stages 0,1
    ISSUE_PLANE(0, 0); cp_commit();
    ISSUE_PLANE(1, 1); cp_commit();

#define STEP(U, ii)                                                           \
    do {                                                                      \
        const int i_ = (ii) + (U);                                            \
        cp_wait1();                                                           \
        __syncthreads();            /* ring data ready; prior stageB done */  \
        const int j_ = i_ + 2;                                                \
        if (j_ < NP) ISSUE_PLANE(j_, ((U) + 2) % 3);                          \
        cp_commit();                                                          \
        stageA_row<(U)>(warp, lane);                                          \
        if (hasA2) stageA_row<(U)>(rowA2, lane);                              \
        __syncthreads();            /* ws/wd ready */                         \
        stageB<(U)>(warp, lane, ss, ds, sd);                                  \
        if (i_ >= 2) z_combine<(U)>(ss, ds, sd, acc);                         \
    } while (0)

    for (int ii = 0; ii < NP; ii += 3) {
        STEP(0, ii);
        STEP(1, ii);
        STEP(2, ii);
    }

    // ---- reduction ----
    float a = (acc.x + acc.y) + (acc.z + acc.w);
#pragma unroll
    for (int off = 16; off > 0; off >>= 1)
        a += __shfl_down_sync(0xffffffffu, a, off);

    if (lane == 0) wsum_sm[warp] = a;
    __syncthreads();
    if (warp == 0) {
        float v = (lane < 8) ? wsum_sm[lane] : 0.0f;
#pragma unroll
        for (int off = 4; off > 0; off >>= 1)
            v += __shfl_down_sync(0xffffffffu, v, off);
        if (lane == 0)
            atomicAdd(out, v * (1.0f / (3.0f * 16.0f * 64.0f * 128.0f * 128.0f)));
    }
}

extern "C" void kernel_launch(void* const* d_in, const int* in_sizes, int n_in,
                              void* d_out, int out_size) {
    const float* pred = (const float*)d_in[0];
    const float* tgt  = (const float*)d_in[1];
    float* out = (float*)d_out;

    sg3d_zero_out<<<1, 1>>>(out);

    dim3 grid(H_DIM / TH, BC_DIM, D_DIM / ZC);   // 16 x 16 x 4 = 1024 blocks
    sg3d_loss_kernel<<<grid, 256>>>(pred, tgt, out);
}

// round 6
// speedup vs baseline: 1.4981x; 1.4981x over previous
#include <cuda_runtime.h>
#include <cstdint>

// SpatialGradientLoss3D = mean |sobel3d(pred - target)| over 3 axes.
// R6: R4 cp.async ring structure (best so far) +
//   (a) packed f32x2 math for diff/w-conv/h-combine/z-combine
//   (b) 4-stage ring, depth-3 prefetch, wait_group 2
//   (c) single launch: per-block partials + last-block reduction (no zero kernel)
// Shapes fixed: (B=4, C=4, D=64, H=128, W=128), fp32, out = 1 float.

#define D_DIM 64
#define H_DIM 128
#define W_DIM 128
#define HW    (H_DIM * W_DIM)
#define BC_DIM 16
#define TH 8
#define PR (TH + 2)
#define ZC 16
#define NP (ZC + 2)             // 18 planes touched
#define NSTAGE 4
#define PLANE_F4 (2 * PR * 32)  // 640 float4 per ring stage (P then T)
#define STAGE_BYTES (PLANE_F4 * 16)
#define NBLK (16 * 16 * 4)      // 1024

typedef unsigned long long F2;  // packed f32x2

__device__ __forceinline__ F2 PACK2(float lo, float hi) {
    F2 r; asm("mov.b64 %0,{%1,%2};" : "=l"(r) : "f"(lo), "f"(hi)); return r;
}
__device__ __forceinline__ void UNPACK2(F2 v, float& lo, float& hi) {
    asm("mov.b64 {%0,%1},%2;" : "=f"(lo), "=f"(hi) : "l"(v));
}
__device__ __forceinline__ F2 ADD2(F2 a, F2 b) {
    F2 r; asm("add.rn.f32x2 %0,%1,%2;" : "=l"(r) : "l"(a), "l"(b)); return r;
}
__device__ __forceinline__ F2 SUB2(F2 a, F2 b) {
    F2 r; asm("sub.rn.f32x2 %0,%1,%2;" : "=l"(r) : "l"(a), "l"(b)); return r;
}
__device__ __forceinline__ F2 FMA2(F2 a, F2 b, F2 c) {
    F2 r; asm("fma.rn.f32x2 %0,%1,%2,%3;" : "=l"(r) : "l"(a), "l"(b), "l"(c)); return r;
}
__device__ __forceinline__ F2 ABS2(F2 a) {
    return a & 0x7FFFFFFF7FFFFFFFULL;
}

__device__ __forceinline__ void cpasync16(uint32_t dst, const float* src, int sz) {
    asm volatile("cp.async.cg.shared.global [%0], [%1], 16, %2;\n"
                 :: "r"(dst), "l"(src), "r"(sz) : "memory");
}
__device__ __forceinline__ void cp_commit() {
    asm volatile("cp.async.commit_group;\n" ::: "memory");
}
__device__ __forceinline__ void cp_wait2() {
    asm volatile("cp.async.wait_group 2;\n" ::: "memory");
}

__shared__ float4 sbuf[NSTAGE][PLANE_F4];
__shared__ float wsum_sm[8];

__device__ float g_partials[NBLK];
__device__ unsigned g_count = 0;

// Consume plane from ring stage STG into z-slot SLOT for this thread's
// 4 output columns (lane) at output row = warp. All math packed f32x2.
template<int STG, int SLOT>
__device__ __forceinline__ void plane_consume(int warp, int lane,
                                              F2 (*ss)[2], F2 (*ds)[2], F2 (*sd)[2],
                                              F2 TWO2, bool l0, bool l31) {
    const ulonglong2* sb = reinterpret_cast<const ulonglong2*>(&sbuf[STG][0]);
    F2 ws[3][2], wd[3][2];
#pragma unroll
    for (int dr = 0; dr < 3; ++dr) {
        ulonglong2 pv = sb[(warp + dr) * 32 + lane];
        ulonglong2 tv = sb[PR * 32 + (warp + dr) * 32 + lane];
        F2 e01 = SUB2(pv.x, tv.x);
        F2 e23 = SUB2(pv.y, tv.y);
        float e0, e1, e2, e3;
        UNPACK2(e01, e0, e1);
        UNPACK2(e23, e2, e3);
        float eL = __shfl_up_sync(0xffffffffu, e3, 1);
        float eR = __shfl_down_sync(0xffffffffu, e0, 1);
        if (l0)  eL = 0.f;
        if (l31) eR = 0.f;
        F2 pm  = PACK2(eL, e0);
        F2 p12 = PACK2(e1, e2);
        F2 pr  = PACK2(e3, eR);
        ws[dr][0] = ADD2(FMA2(e01, TWO2, pm),  p12);
        ws[dr][1] = ADD2(FMA2(e23, TWO2, p12), pr);
        wd[dr][0] = SUB2(p12, pm);
        wd[dr][1] = SUB2(pr, p12);
    }
#pragma unroll
    for (int h = 0; h < 2; ++h) {
        ss[SLOT][h] = ADD2(FMA2(ws[1][h], TWO2, ws[0][h]), ws[2][h]);
        ds[SLOT][h] = SUB2(ws[2][h], ws[0][h]);
        sd[SLOT][h] = ADD2(FMA2(wd[1][h], TWO2, wd[0][h]), wd[2][h]);
    }
}

template<int SP>
__device__ __forceinline__ void z_combine(const F2 (*ss)[2], const F2 (*ds)[2],
                                          const F2 (*sd)[2], F2* acc, F2 TWO2) {
    constexpr int SM = (SP + 1) % 3;
    constexpr int S0 = (SP + 2) % 3;
#pragma unroll
    for (int h = 0; h < 2; ++h) {
        F2 gd = SUB2(ss[SP][h], ss[SM][h]);
        F2 gh = ADD2(FMA2(ds[S0][h], TWO2, ds[SM][h]), ds[SP][h]);
        F2 gw = ADD2(FMA2(sd[S0][h], TWO2, sd[SM][h]), sd[SP][h]);
        acc[h] = ADD2(acc[h], ABS2(gd));
        acc[h] = ADD2(acc[h], ABS2(gh));
        acc[h] = ADD2(acc[h], ABS2(gw));
    }
}

__global__ __launch_bounds__(256, 3)
void sg3d_loss_kernel(const float* __restrict__ pred,
                      const float* __restrict__ tgt,
                      float* __restrict__ out) {
    const int tid  = threadIdx.x;
    const int lane = tid & 31;
    const int warp = tid >> 5;
    const bool l0  = (lane == 0);
    const bool l31 = (lane == 31);

    const int h0 = blockIdx.x * TH;
    const int bc = blockIdx.y;
    const int z0 = blockIdx.z * ZC;
    const int bid = blockIdx.x + (blockIdx.y << 4) + (blockIdx.z << 8);

    const size_t base = (size_t)bc * D_DIM * HW;
    const float* P = pred + base;
    const float* T = tgt + base;

    uint32_t smem_base;
    asm("{ .reg .u64 t; cvta.to.shared.u64 t, %1; cvt.u32.u64 %0, t; }"
        : "=r"(smem_base) : "l"((const void*)&sbuf[0][0]));

    // per-slot cp.async params (slot k covers idx = tid + 256k)
    const float* gp[3];
    uint32_t saddr[3];
    int rowok[3], active[3];
#pragma unroll
    for (int k = 0; k < 3; ++k) {
        int idx = tid + 256 * k;
        active[k] = idx < PLANE_F4;
        int a   = idx >= PR * 32;
        int rel = idx - a * PR * 32;
        int row = rel >> 5;
        int c4  = rel & 31;
        int gh  = h0 - 1 + row;
        rowok[k] = (unsigned)gh < (unsigned)H_DIM;
        int soff = (rowok[k] ? gh : 0) * W_DIM + c4 * 4;
        gp[k] = (a ? T : P) + soff;
        saddr[k] = smem_base + (uint32_t)idx * 16u;
    }

#define ISSUE_PLANE(J, STAGE)                                                 \
    do {                                                                      \
        int gz_ = z0 - 1 + (J);                                               \
        int zok_ = (unsigned)gz_ < (unsigned)D_DIM;                           \
        int gzc_ = zok_ ? gz_ : 0;                                            \
        _Pragma("unroll")                                                     \
        for (int k = 0; k < 3; ++k) {                                         \
            if (active[k]) {                                                  \
                int sz_ = (rowok[k] & zok_) ? 16 : 0;                         \
                cpasync16(saddr[k] + (STAGE) * STAGE_BYTES,                   \
                          gp[k] + (size_t)gzc_ * HW, sz_);                    \
            }                                                                 \
        }                                                                     \
    } while (0)

    const F2 TWO2 = 0x4000000040000000ULL;
    F2 ss[3][2], ds[3][2], sd[3][2];
    F2 acc[2] = {0ULL, 0ULL};

    // prologue: planes 0,1,2 -> stages 0,1,2
    ISSUE_PLANE(0, 0); cp_commit();
    ISSUE_PLANE(1, 1); cp_commit();
    ISSUE_PLANE(2, 2); cp_commit();

#define STEP(I)                                                               \
    do {                                                                      \
        cp_wait2();                                                           \
        __syncthreads();                                                      \
        if ((I) + 3 < NP) ISSUE_PLANE((I) + 3, ((I) + 3) % NSTAGE);           \
        cp_commit();                                                          \
        plane_consume<(I) % NSTAGE, (I) % 3>(warp, lane, ss, ds, sd,          \
                                             TWO2, l0, l31);                  \
        if ((I) >= 2) z_combine<(I) % 3>(ss, ds, sd, acc, TWO2);              \
    } while (0)

    STEP(0);  STEP(1);  STEP(2);  STEP(3);  STEP(4);  STEP(5);
    STEP(6);  STEP(7);  STEP(8);  STEP(9);  STEP(10); STEP(11);
    STEP(12); STEP(13); STEP(14); STEP(15); STEP(16); STEP(17);

    // ---- block reduction ----
    float ax, ay, az, aw;
    UNPACK2(acc[0], ax, ay);
    UNPACK2(acc[1], az, aw);
    float a = (ax + ay) + (az + aw);
#pragma unroll
    for (int off = 16; off > 0; off >>= 1)
        a += __shfl_down_sync(0xffffffffu, a, off);

    if (lane == 0) wsum_sm[warp] = a;
    __syncthreads();

    __shared__ bool is_last;
    if (tid == 0) {
        float v = 0.f;
#pragma unroll
        for (int w = 0; w < 8; ++w) v += wsum_sm[w];
        g_partials[bid] = v;
        __threadfence();
        unsigned old = atomicAdd(&g_count, 1u);
        is_last = (old == NBLK - 1);
    }
    __syncthreads();

    // ---- last block reduces all partials, writes out, resets counter ----
    if (is_last) {
        __threadfence();
        const volatile float* pv = g_partials;
        float s = 0.f;
#pragma unroll
        for (int k = 0; k < NBLK / 256; ++k)
            s += pv[tid + 256 * k];
#pragma unroll
        for (int off = 16; off > 0; off >>= 1)
            s += __shfl_down_sync(0xffffffffu, s, off);
        if (lane == 0) wsum_sm[warp] = s;
        __syncthreads();
        if (tid == 0) {
            float v = 0.f;
#pragma unroll
            for (int w = 0; w < 8; ++w) v += wsum_sm[w];
            out[0] = v * (1.0f / (3.0f * 16.0f * 64.0f * 128.0f * 128.0f));
            g_count = 0;            // reset for next graph replay
        }
    }
}

extern "C" void kernel_launch(void* const* d_in, const int* in_sizes, int n_in,
                              void* d_out, int out_size) {
    const float* pred = (const float*)d_in[0];
    const float* tgt  = (const float*)d_in[1];
    float* out = (float*)d_out;

    dim3 grid(H_DIM / TH, BC_DIM, D_DIM / ZC);   // 16 x 16 x 4 = 1024 blocks
    sg3d_loss_kernel<<<grid, 256>>>(pred, tgt, out);
}